// round 2
// baseline (speedup 1.0000x reference)
#include <cuda_runtime.h>

#define BATCH 8
#define SEQ   2048
#define DIN   1024
#define DHEAD 128
#define NROWS (BATCH * SEQ)

// Scratch for projected q/k/v (allocation-free rule: use __device__ globals)
__device__ float g_q[NROWS * DHEAD];
__device__ float g_k[NROWS * DHEAD];
__device__ float g_v[NROWS * DHEAD];

// ---------------------------------------------------------------------------
// Projection GEMM: Y[16384,128] = X[16384,1024] @ W[1024,128] + b
// 64x128 tile per block, BK=16, 256 threads, 4x8 register micro-tile.
// grid = (256, 3); blockIdx.y selects which of q/k/v projection to compute.
// ---------------------------------------------------------------------------
__global__ __launch_bounds__(256) void proj_kernel(
    const float* __restrict__ Xq, const float* __restrict__ Xk, const float* __restrict__ Xv,
    const float* __restrict__ Wq, const float* __restrict__ Wk, const float* __restrict__ Wv,
    const float* __restrict__ bq, const float* __restrict__ bk, const float* __restrict__ bv)
{
    const float* X;
    const float* W;
    const float* bias;
    float* Y;
    if (blockIdx.y == 0)      { X = Xq; W = Wq; bias = bq; Y = g_q; }
    else if (blockIdx.y == 1) { X = Xk; W = Wk; bias = bk; Y = g_k; }
    else                      { X = Xv; W = Wv; bias = bv; Y = g_v; }

    __shared__ float As[16][64];    // k-major A tile (transposed on store)
    __shared__ float Bs[16][128];

    const int row0 = blockIdx.x * 64;
    const int t  = threadIdx.x;
    const int ty = t >> 4;          // 0..15 (m)
    const int tx = t & 15;          // 0..15 (n)

    float acc[4][8];
#pragma unroll
    for (int i = 0; i < 4; i++)
#pragma unroll
        for (int j = 0; j < 8; j++) acc[i][j] = 0.f;

    const int ar = t >> 2;          // 0..63  A row
    const int ak = (t & 3) << 2;    // 0,4,8,12  A k offset
    const int bn = (t & 31) << 2;   // B col (float) for f4 load
    const int bk0 = t >> 5;         // B k row (first of two)

    for (int k0 = 0; k0 < DIN; k0 += 16) {
        // stage from global first (hide latency), then sync, then smem store
        float4 a4 = *reinterpret_cast<const float4*>(X + (size_t)(row0 + ar) * DIN + k0 + ak);
        float4 b4a = *reinterpret_cast<const float4*>(W + (size_t)(k0 + bk0) * DHEAD + bn);
        float4 b4b = *reinterpret_cast<const float4*>(W + (size_t)(k0 + 8 + bk0) * DHEAD + bn);

        __syncthreads();
        As[ak + 0][ar] = a4.x;
        As[ak + 1][ar] = a4.y;
        As[ak + 2][ar] = a4.z;
        As[ak + 3][ar] = a4.w;
        *reinterpret_cast<float4*>(&Bs[bk0][bn])     = b4a;
        *reinterpret_cast<float4*>(&Bs[bk0 + 8][bn]) = b4b;
        __syncthreads();

#pragma unroll
        for (int kk = 0; kk < 16; kk++) {
            float4 av  = *reinterpret_cast<const float4*>(&As[kk][ty << 2]);
            float4 bv0 = *reinterpret_cast<const float4*>(&Bs[kk][tx << 3]);
            float4 bv1 = *reinterpret_cast<const float4*>(&Bs[kk][(tx << 3) + 4]);
            float a_[4] = {av.x, av.y, av.z, av.w};
            float b_[8] = {bv0.x, bv0.y, bv0.z, bv0.w, bv1.x, bv1.y, bv1.z, bv1.w};
#pragma unroll
            for (int i = 0; i < 4; i++)
#pragma unroll
                for (int j = 0; j < 8; j++)
                    acc[i][j] += a_[i] * b_[j];
        }
    }

#pragma unroll
    for (int i = 0; i < 4; i++) {
        float* yp = Y + (size_t)(row0 + (ty << 2) + i) * DHEAD + (tx << 3);
#pragma unroll
        for (int j = 0; j < 8; j++)
            yp[j] = acc[i][j] + bias[(tx << 3) + j];
    }
}

// ---------------------------------------------------------------------------
// Flash attention: grid (SEQ/64, BATCH), 256 threads.
// 64 query rows per CTA; each row owned by a 4-lane quad (32 dims each).
// K/V tiles (64x128) in dynamic smem with skewed layout for conflict-free
// float4 LDS: phys = row*140 + d + 4*(d>>5)   (maps d in [0,128) -> [0,140))
// Online softmax in 16-key chunks (keeps p[] at 16 regs).
// ---------------------------------------------------------------------------
#define KT 64
#define KSTRIDE 140   // 128 + 12 skew span + 4 tail pad  (FIX: was 132 -> OOB)

__global__ __launch_bounds__(256) void attn_kernel(float* __restrict__ O)
{
    extern __shared__ float sm[];
    float* Ks = sm;
    float* Vs = sm + KT * KSTRIDE;

    const int b    = blockIdx.y;
    const int q0   = blockIdx.x * 64;
    const int t    = threadIdx.x;
    const int row  = t >> 2;
    const int quad = t & 3;
    const int d0   = quad << 5;

    const float scale = 0.088388347648318447f;  // 1/sqrt(128)

    float qreg[32];
    const float* qp = g_q + ((size_t)(b * SEQ + q0 + row)) * DHEAD + d0;
#pragma unroll
    for (int i = 0; i < 32; i++) qreg[i] = qp[i] * scale;

    float acc[32];
#pragma unroll
    for (int i = 0; i < 32; i++) acc[i] = 0.f;
    float m = -1e30f, l = 0.f;

    const float* kb = g_k + (size_t)b * SEQ * DHEAD;
    const float* vb = g_v + (size_t)b * SEQ * DHEAD;

    const int skew = d0 + (quad << 2);  // = 36*quad floats, 16B aligned

    for (int j0 = 0; j0 < SEQ; j0 += KT) {
        __syncthreads();
        // load K,V tiles: 2048 float4 each; 8 per thread per tile
#pragma unroll
        for (int u = 0; u < 8; u++) {
            int f4 = t + u * 256;
            int r  = f4 >> 5;
            int dc = (f4 & 31) << 2;
            int off = r * KSTRIDE + dc + ((dc >> 5) << 2);
            *reinterpret_cast<float4*>(Ks + off) =
                *reinterpret_cast<const float4*>(kb + (size_t)(j0 + r) * DHEAD + dc);
            *reinterpret_cast<float4*>(Vs + off) =
                *reinterpret_cast<const float4*>(vb + (size_t)(j0 + r) * DHEAD + dc);
        }
        __syncthreads();

        for (int c = 0; c < 4; c++) {  // 16-key chunks within tile
            float p[16];
            float tmax = -1e30f;
#pragma unroll
            for (int jj = 0; jj < 16; jj++) {
                const float* kr = Ks + ((c << 4) + jj) * KSTRIDE + skew;
                float s0 = 0.f, s1 = 0.f, s2 = 0.f, s3 = 0.f;
#pragma unroll
                for (int i = 0; i < 32; i += 4) {
                    float4 kv = *reinterpret_cast<const float4*>(kr + i);
                    s0 += qreg[i]     * kv.x;
                    s1 += qreg[i + 1] * kv.y;
                    s2 += qreg[i + 2] * kv.z;
                    s3 += qreg[i + 3] * kv.w;
                }
                float s = (s0 + s1) + (s2 + s3);
                s += __shfl_xor_sync(0xffffffffu, s, 1);
                s += __shfl_xor_sync(0xffffffffu, s, 2);
                p[jj] = s;
                tmax = fmaxf(tmax, s);
            }

            float mnew  = fmaxf(m, tmax);
            float alpha = __expf(m - mnew);
            m = mnew;
            float lsum = 0.f;
#pragma unroll
            for (int jj = 0; jj < 16; jj++) {
                p[jj] = __expf(p[jj] - mnew);
                lsum += p[jj];
            }
            l = l * alpha + lsum;
#pragma unroll
            for (int i = 0; i < 32; i++) acc[i] *= alpha;

#pragma unroll
            for (int jj = 0; jj < 16; jj++) {
                const float* vr = Vs + ((c << 4) + jj) * KSTRIDE + skew;
                float pj = p[jj];
#pragma unroll
                for (int i = 0; i < 32; i += 4) {
                    float4 vv = *reinterpret_cast<const float4*>(vr + i);
                    acc[i]     += pj * vv.x;
                    acc[i + 1] += pj * vv.y;
                    acc[i + 2] += pj * vv.z;
                    acc[i + 3] += pj * vv.w;
                }
            }
        }
    }

    const float inv = 1.f / l;
    float* op = O + ((size_t)(b * SEQ + q0 + row)) * DHEAD + d0;
#pragma unroll
    for (int i = 0; i < 32; i++) op[i] = acc[i] * inv;
}

// ---------------------------------------------------------------------------
extern "C" void kernel_launch(void* const* d_in, const int* in_sizes, int n_in,
                              void* d_out, int out_size)
{
    const float* query = (const float*)d_in[0];
    const float* key   = (const float*)d_in[1];
    const float* value = (const float*)d_in[2];
    const float* Wq    = (const float*)d_in[3];
    const float* bq    = (const float*)d_in[4];
    const float* Wk    = (const float*)d_in[5];
    const float* bk    = (const float*)d_in[6];
    const float* Wv    = (const float*)d_in[7];
    const float* bv    = (const float*)d_in[8];

    const int smem_bytes = 2 * KT * KSTRIDE * sizeof(float);  // 71680
    cudaFuncSetAttribute(attn_kernel, cudaFuncAttributeMaxDynamicSharedMemorySize, smem_bytes);

    dim3 pgrid(NROWS / 64, 3);
    proj_kernel<<<pgrid, 256>>>(query, key, value, Wq, Wk, Wv, bq, bk, bv);

    dim3 agrid(SEQ / 64, BATCH);
    attn_kernel<<<agrid, 256, smem_bytes>>>((float*)d_out);
}